// round 4
// baseline (speedup 1.0000x reference)
#include <cuda_runtime.h>

#define NN 8192
#define FF 128
#define EE 262144
#define METAL 64
#define NOUT 17
#define TWO_N (2*NN)
#define TWO_E (2*EE)
#define KSPLIT 128
#define KCHUNK (TWO_N / KSPLIT)   // 128
#define GRID 592                  // 4 blocks/SM on 148 SMs (<= capacity, co-resident)
#define TPB 256
#define NTHREADS (GRID * TPB)

// ---- scratch (device globals: no allocation allowed) ----
__device__ float d_deg[TWO_N];
__device__ float d_dinv[TWO_N];
__device__ float d_gv[4][TWO_N];   // per-round g buffers (L1-staleness avoidance)
__device__ float d_yv[4][TWO_N];   // per-round y buffers
__device__ float d_res[NN];        // result_inter partials (zeroed in setup phase)
__device__ float d_wc[FF];         // W1@W2@W3@W4
__device__ float d_c[4];           // c1, c2, c3, b4

// ---- device-wide barrier state (replay-safe: epoch monotonically grows) ----
__device__ unsigned bar_ctr = 0;
__device__ unsigned bar_epoch = 0;

__device__ __forceinline__ void gbar() {
    __syncthreads();
    if (threadIdx.x == 0) {
        __threadfence();                                   // publish our writes
        unsigned e = *(volatile unsigned*)&bar_epoch;      // read epoch BEFORE arrive
        __threadfence();                                   // order e-read vs atomic
        if (atomicAdd(&bar_ctr, 1) == GRID - 1) {
            bar_ctr = 0;                                   // no concurrent arrivals left
            __threadfence();
            atomicAdd(&bar_epoch, 1);                      // release
        } else {
            while (*(volatile unsigned*)&bar_epoch == e) __nanosleep(64);
        }
        __threadfence();
    }
    __syncthreads();
}

// ================= ONE persistent kernel for the whole GCN side =================
__global__ void __launch_bounds__(TPB, 4) k_gcn(
    const float* __restrict__ x1, const float* __restrict__ x2,
    const float* __restrict__ W1, const float* __restrict__ b1,
    const float* __restrict__ W2, const float* __restrict__ b2,
    const float* __restrict__ W3, const float* __restrict__ b3,
    const float* __restrict__ W4, const float* __restrict__ b4,
    const int* __restrict__ ei1, const int* __restrict__ ei2)
{
    const int tid = blockIdx.x * TPB + threadIdx.x;
    const int Q = EE / 4;

    // ---- phase 0: deg=1 (self-loop), res=0, combined weights ----
    for (int i = tid; i < TWO_N; i += NTHREADS) d_deg[i] = 1.0f;
    for (int i = tid; i < NN; i += NTHREADS)    d_res[i] = 0.0f;
    if (blockIdx.x == 0 && threadIdx.x < FF) {
        int f = threadIdx.x;
        float w34[4], w234[8];
#pragma unroll
        for (int c = 0; c < 4; c++)
            w34[c] = W3[c * 2 + 0] * W4[0] + W3[c * 2 + 1] * W4[1];
#pragma unroll
        for (int r = 0; r < 8; r++) {
            float s = 0.0f;
#pragma unroll
            for (int c = 0; c < 4; c++) s += W2[r * 4 + c] * w34[c];
            w234[r] = s;
        }
        float s = 0.0f;
#pragma unroll
        for (int r = 0; r < 8; r++) s += W1[f * 8 + r] * w234[r];
        d_wc[f] = s;
        if (f == 0) {
            float c1 = 0.0f, c2 = 0.0f;
#pragma unroll
            for (int r = 0; r < 8; r++) c1 += b1[r] * w234[r];
#pragma unroll
            for (int c = 0; c < 4; c++) c2 += b2[c] * w34[c];
            d_c[0] = c1;
            d_c[1] = c2;
            d_c[2] = b3[0] * W4[0] + b3[1] * W4[1];
            d_c[3] = b4[0];
        }
    }
    gbar();

    // ---- phase 1: degree count (4 edges/thread-item) ----
    for (int t = tid; t < 2 * Q; t += NTHREADS) {
        int4 dd; int off;
        if (t < Q) { dd = ((const int4*)(ei1 + EE))[t];     off = 0;  }
        else       { dd = ((const int4*)(ei2 + EE))[t - Q]; off = NN; }
        atomicAdd(&d_deg[off + dd.x], 1.0f);
        atomicAdd(&d_deg[off + dd.y], 1.0f);
        atomicAdd(&d_deg[off + dd.z], 1.0f);
        atomicAdd(&d_deg[off + dd.w], 1.0f);
    }
    gbar();

    // ---- phase 2: dinv = rsqrt(deg); g0 = dinv*(x@wc); y0 = g0 (warp/node) ----
    __shared__ float swc[FF];
    if (threadIdx.x < FF) swc[threadIdx.x] = d_wc[threadIdx.x];
    __syncthreads();
    {
        const int w = tid >> 5, lane = tid & 31, NW = NTHREADS >> 5;
        float4 wv = ((const float4*)swc)[lane];
        for (int i = w; i < TWO_N; i += NW) {
            const float* x = (i < NN) ? (x1 + (size_t)i * FF)
                                      : (x2 + (size_t)(i - NN) * FF);
            float4 v = ((const float4*)x)[lane];
            float s = v.x * wv.x + v.y * wv.y + v.z * wv.z + v.w * wv.w;
#pragma unroll
            for (int o = 16; o > 0; o >>= 1) s += __shfl_xor_sync(0xffffffff, s, o);
            if (lane == 0) {
                float dv = rsqrtf(d_deg[i]);
                d_dinv[i] = dv;
                float g = dv * s;
                d_gv[0][i] = g;
                d_yv[0][i] = g;
            }
        }
    }
    gbar();

    // ---- phases 3..: four scalar propagation rounds ----
    for (int r = 0; r < 4; r++) {
        const float* gsrc = d_gv[r];
        float*       ydst = d_yv[r];
        // scatter: y_r[dst] += g_r[src]
        for (int t = tid; t < 2 * Q; t += NTHREADS) {
            int4 s4, d4; int off;
            if (t < Q) {
                s4 = ((const int4*)ei1)[t];       d4 = ((const int4*)(ei1 + EE))[t];       off = 0;
            } else {
                s4 = ((const int4*)ei2)[t - Q];   d4 = ((const int4*)(ei2 + EE))[t - Q];   off = NN;
            }
            float g0 = gsrc[off + s4.x];
            float g1 = gsrc[off + s4.y];
            float g2 = gsrc[off + s4.z];
            float g3 = gsrc[off + s4.w];
            atomicAdd(&ydst[off + d4.x], g0);
            atomicAdd(&ydst[off + d4.y], g1);
            atomicAdd(&ydst[off + d4.z], g2);
            atomicAdd(&ydst[off + d4.w], g3);
        }
        if (r < 3) {
            gbar();
            // node update: g_{r+1} = y_{r+1} = dinv*(dinv*y_r + c_r)
            float cr = d_c[r];
            for (int i = tid; i < TWO_N; i += NTHREADS) {
                float dv = d_dinv[i];
                float g = dv * (dv * d_yv[r][i] + cr);
                d_gv[r + 1][i] = g;
                d_yv[r + 1][i] = g;
            }
            gbar();
        }
        // r==3: y3 finalized by atomics; consumed by next LAUNCH (implicit sync)
    }
}

// ---- big GEMV: res[j] += sum_k h[k]*Wi[k*N+j]; h = dinv*y3 + c3 on the fly.
//      block (0,0) also initializes out = bf + meta @ Wf[N:]
__global__ void __launch_bounds__(TPB) k_wi_gemv(
    const float* __restrict__ Wi, const float* __restrict__ meta,
    const float* __restrict__ Wf, const float* __restrict__ bf,
    float* __restrict__ out)
{
    __shared__ float sh[KCHUNK];
    int k0 = blockIdx.y * KCHUNK;
    if (threadIdx.x < KCHUNK) {
        int k = k0 + threadIdx.x;
        sh[threadIdx.x] = d_dinv[k] * d_yv[3][k] + d_c[3];
    }
    __syncthreads();
    int j4 = blockIdx.x * blockDim.x + threadIdx.x;   // float4 column index
    const float4* Wi4 = (const float4*)Wi;
    float4 acc = make_float4(0.f, 0.f, 0.f, 0.f);
#pragma unroll 8
    for (int kk = 0; kk < KCHUNK; kk++) {
        float c = sh[kk];
        float4 w = __ldcs(&Wi4[(size_t)(k0 + kk) * (NN / 4) + j4]);
        acc.x += c * w.x; acc.y += c * w.y; acc.z += c * w.z; acc.w += c * w.w;
    }
    int j = j4 * 4;
    atomicAdd(&d_res[j + 0], acc.x);
    atomicAdd(&d_res[j + 1], acc.y);
    atomicAdd(&d_res[j + 2], acc.z);
    atomicAdd(&d_res[j + 3], acc.w);
    if (blockIdx.x == 0 && blockIdx.y == 0 && threadIdx.x < NOUT) {
        int jj = threadIdx.x;
        float s = bf[jj];
#pragma unroll 8
        for (int m = 0; m < METAL; m++)
            s += meta[m] * Wf[(size_t)(NN + m) * NOUT + jj];
        out[jj] = s;
    }
}

// ---------------- out += (res + bi) @ Wf[:N]   (bi folded here)
__global__ void k_out_acc(const float* __restrict__ Wf,
                          const float* __restrict__ bi,
                          float* __restrict__ out) {
    int i = blockIdx.x * blockDim.x + threadIdx.x;   // exactly NN threads
    float r = d_res[i] + bi[i];
    float acc[NOUT];
#pragma unroll
    for (int j = 0; j < NOUT; j++) acc[j] = r * Wf[(size_t)i * NOUT + j];
#pragma unroll
    for (int j = 0; j < NOUT; j++) {
#pragma unroll
        for (int o = 16; o > 0; o >>= 1)
            acc[j] += __shfl_xor_sync(0xffffffff, acc[j], o);
    }
    if ((threadIdx.x & 31) == 0) {
#pragma unroll
        for (int j = 0; j < NOUT; j++) atomicAdd(&out[j], acc[j]);
    }
}

// ================================================================= launch
extern "C" void kernel_launch(void* const* d_in, const int* in_sizes, int n_in,
                              void* d_out, int out_size) {
    const float* x1   = (const float*)d_in[0];
    const float* x2   = (const float*)d_in[1];
    const float* meta = (const float*)d_in[2];
    const float* W1   = (const float*)d_in[3];
    const float* b1   = (const float*)d_in[4];
    const float* W2   = (const float*)d_in[5];
    const float* b2   = (const float*)d_in[6];
    const float* W3   = (const float*)d_in[7];
    const float* b3   = (const float*)d_in[8];
    const float* W4   = (const float*)d_in[9];
    const float* b4   = (const float*)d_in[10];
    const float* Wi   = (const float*)d_in[11];
    const float* bi   = (const float*)d_in[12];
    const float* Wf   = (const float*)d_in[13];
    const float* bf   = (const float*)d_in[14];
    const int*   ei1  = (const int*)d_in[15];
    const int*   ei2  = (const int*)d_in[16];
    float* out = (float*)d_out;

    // 1) whole GCN side in one persistent kernel
    k_gcn<<<GRID, TPB>>>(x1, x2, W1, b1, W2, b2, W3, b3, W4, b4, ei1, ei2);
    // 2) res = h @ Wi (k-split, atomics); also inits out with bf + meta part
    {
        dim3 grid(NN / (TPB * 4), KSPLIT);
        k_wi_gemv<<<grid, TPB>>>(Wi, meta, Wf, bf, out);
    }
    // 3) out += (res + bi) @ Wf[:N]
    k_out_acc<<<NN / TPB, TPB>>>(Wf, bi, out);
}